// round 14
// baseline (speedup 1.0000x reference)
#include <cuda_runtime.h>
#include <cuda_bf16.h>
#include <math.h>

#define BB 64
#define TT 2048
#define II 256
#define HH 512
#define G3 1536          // 3*H

// recurrent grid: 16 j-CTAs x 8 b-groups = 128 CTAs (co-resident)
#define NJ 16            // j-blocks (32 j each)
#define NB 8             // b-groups (8 b each)
#define BLK_R 256        // 8 warps; warp = 64-k slice (4 k-tiles of 16)

// gru smem (bytes):
//   [0, 98304)        A hi fragments: uint4[6*32*32]  (96 KB)
//   [98304, 196608)   A lo fragments
//   [196608, 221184)  H bf16 hi/lo planes (16 rows x 520 elems x 2 B = 16640 B)
//                     aliased by partials float[8*96*8] = 24576 B
#define S_AHI 0
#define S_ALO 98304
#define S_HP  196608
#define SMEM_BYTES (196608 + 24576)   // 221184 <= 232448

// ig tensor kernel smem (floats), padded stride 68 for conflict-free frags
#define WST   68
#define S_WHI 0
#define S_WLO 8704
#define S_XHI 17408
#define S_XLO 21760
#define IGT_SMEMF 26112
#define IGT_SMEMB (IGT_SMEMF * 4)

// ---------------- scratch ----------------
__device__ float g_ig[(size_t)TT * G3 * BB];           // [t][j][b]
__device__ __align__(16) unsigned char g_h2[NB][2][16384]; // [buf]: 16 rows(plane*8+b) x 1024 B
__device__ unsigned g_flags2[NB * NJ * 64];            // 256-B padded flags

// ---------------- helpers ----------------
__device__ __forceinline__ float sigmoidf_(float x) {
    return 1.0f / (1.0f + expf(-x));
}
__device__ __forceinline__ void cp16(unsigned dst, const void* src) {
    asm volatile("cp.async.cg.shared.global [%0], [%1], 16;" :: "r"(dst), "l"(src));
}
__device__ __forceinline__ unsigned f2tf32(float x) {
    unsigned u;
    asm("cvt.rna.tf32.f32 %0, %1;" : "=r"(u) : "f"(x));
    return u;
}
__device__ __forceinline__ void mma_tf32(float* c, const unsigned* a, const unsigned* b) {
    asm volatile(
        "mma.sync.aligned.m16n8k8.row.col.f32.tf32.tf32.f32 "
        "{%0,%1,%2,%3}, {%4,%5,%6,%7}, {%8,%9}, {%0,%1,%2,%3};"
        : "+f"(c[0]), "+f"(c[1]), "+f"(c[2]), "+f"(c[3])
        : "r"(a[0]), "r"(a[1]), "r"(a[2]), "r"(a[3]), "r"(b[0]), "r"(b[1]));
}
__device__ __forceinline__ void mma_bf16(float* c, uint4 a, unsigned b0, unsigned b1) {
    asm volatile(
        "mma.sync.aligned.m16n8k16.row.col.f32.bf16.bf16.f32 "
        "{%0,%1,%2,%3}, {%4,%5,%6,%7}, {%8,%9}, {%0,%1,%2,%3};"
        : "+f"(c[0]), "+f"(c[1]), "+f"(c[2]), "+f"(c[3])
        : "r"(a.x), "r"(a.y), "r"(a.z), "r"(a.w), "r"(b0), "r"(b1));
}
__device__ __forceinline__ void bsplit(float x, __nv_bfloat16& h, __nv_bfloat16& l) {
    h = __float2bfloat16_rn(x);
    l = __float2bfloat16_rn(x - __bfloat162float(h));
}
__device__ __forceinline__ unsigned pack2(__nv_bfloat16 e0, __nv_bfloat16 e1) {
    // low 16 bits = smaller-k element
    return (unsigned)__bfloat16_as_ushort(e0) | ((unsigned)__bfloat16_as_ushort(e1) << 16);
}

// ---------------- reset ----------------
__global__ void reset_kernel() {
    int idx = blockIdx.x * blockDim.x + threadIdx.x;
    if (idx < NB * NJ) g_flags2[idx * 64] = 0;
}

// ---------------- phase 1: IG via tf32-split tensor cores (unchanged from R13) ----------------
__global__ void __launch_bounds__(256, 2)
ig_tensor_kernel(const float* __restrict__ xs,
                 const float* __restrict__ w_ih,
                 const float* __restrict__ bias) {
    extern __shared__ __align__(16) float sm[];
    float* Whi = sm + S_WHI;
    float* Wlo = sm + S_WLO;
    float* Xhi = sm + S_XHI;
    float* Xlo = sm + S_XLO;

    const int t    = blockIdx.x;
    const int jb   = blockIdx.y * 128;
    const int tid  = threadIdx.x;
    const int warp = tid >> 5;
    const int lane = tid & 31;
    const int wj   = warp >> 1;
    const int wb   = warp & 1;
    const int g    = lane >> 2;
    const int iq   = lane & 3;

    float acc[2][4][4];
#pragma unroll
    for (int mt = 0; mt < 2; mt++)
#pragma unroll
        for (int nt = 0; nt < 4; nt++)
#pragma unroll
            for (int e = 0; e < 4; e++) acc[mt][nt][e] = 0.0f;

    for (int kc = 0; kc < II; kc += 64) {
        {
            int r = tid >> 1, hf = tid & 1;
            const float* src = w_ih + (size_t)(jb + r) * II + kc + hf * 32;
            float* dh = Whi + r * WST + hf * 32;
            float* dl = Wlo + r * WST + hf * 32;
#pragma unroll
            for (int q = 0; q < 8; q++) {
                float4 v = *(const float4*)(src + q * 4);
                float xv[4] = {v.x, v.y, v.z, v.w};
#pragma unroll
                for (int e = 0; e < 4; e++) {
                    unsigned hu = f2tf32(xv[e]);
                    float hif = __uint_as_float(hu);
                    dh[q * 4 + e] = hif;
                    dl[q * 4 + e] = __uint_as_float(f2tf32(xv[e] - hif));
                }
            }
        }
        {
            int b = tid >> 2, q = tid & 3;
            const float* src = xs + ((size_t)b * TT + t) * II + kc + q * 16;
#pragma unroll
            for (int v = 0; v < 4; v++) {
                float4 x4 = *(const float4*)(src + v * 4);
                float xv[4] = {x4.x, x4.y, x4.z, x4.w};
                int k = q * 16 + v * 4;
#pragma unroll
                for (int e = 0; e < 4; e++) {
                    unsigned hu = f2tf32(xv[e]);
                    float hif = __uint_as_float(hu);
                    Xhi[(k + e) * WST + b] = hif;
                    Xlo[(k + e) * WST + b] = __uint_as_float(f2tf32(xv[e] - hif));
                }
            }
        }
        __syncthreads();

#pragma unroll
        for (int ks = 0; ks < 8; ks++) {
            const int k0 = ks * 8;
            unsigned ah[2][4], al[2][4];
#pragma unroll
            for (int mt = 0; mt < 2; mt++) {
                int jr = wj * 32 + mt * 16;
                ah[mt][0] = __float_as_uint(Whi[(jr + g)     * WST + k0 + iq]);
                ah[mt][1] = __float_as_uint(Whi[(jr + g + 8) * WST + k0 + iq]);
                ah[mt][2] = __float_as_uint(Whi[(jr + g)     * WST + k0 + iq + 4]);
                ah[mt][3] = __float_as_uint(Whi[(jr + g + 8) * WST + k0 + iq + 4]);
                al[mt][0] = __float_as_uint(Wlo[(jr + g)     * WST + k0 + iq]);
                al[mt][1] = __float_as_uint(Wlo[(jr + g + 8) * WST + k0 + iq]);
                al[mt][2] = __float_as_uint(Wlo[(jr + g)     * WST + k0 + iq + 4]);
                al[mt][3] = __float_as_uint(Wlo[(jr + g + 8) * WST + k0 + iq + 4]);
            }
            unsigned bh[4][2], bl[4][2];
#pragma unroll
            for (int nt = 0; nt < 4; nt++) {
                int bc = wb * 32 + nt * 8;
                bh[nt][0] = __float_as_uint(Xhi[(k0 + iq)     * WST + bc + g]);
                bh[nt][1] = __float_as_uint(Xhi[(k0 + iq + 4) * WST + bc + g]);
                bl[nt][0] = __float_as_uint(Xlo[(k0 + iq)     * WST + bc + g]);
                bl[nt][1] = __float_as_uint(Xlo[(k0 + iq + 4) * WST + bc + g]);
            }
#pragma unroll
            for (int mt = 0; mt < 2; mt++)
#pragma unroll
                for (int nt = 0; nt < 4; nt++) {
                    mma_tf32(acc[mt][nt], ah[mt], bh[nt]);
                    mma_tf32(acc[mt][nt], ah[mt], bl[nt]);
                    mma_tf32(acc[mt][nt], al[mt], bh[nt]);
                }
        }
        __syncthreads();
    }

#pragma unroll
    for (int mt = 0; mt < 2; mt++) {
#pragma unroll
        for (int rr = 0; rr < 2; rr++) {
            int j = jb + wj * 32 + mt * 16 + g + rr * 8;
            float bj = bias[j];
#pragma unroll
            for (int nt = 0; nt < 4; nt++) {
                int bc = wb * 32 + nt * 8 + 2 * iq;
                float2 o = make_float2(acc[mt][nt][rr * 2 + 0] + bj,
                                       acc[mt][nt][rr * 2 + 1] + bj);
                *(float2*)&g_ig[((size_t)t * G3 + j) * BB + bc] = o;
            }
        }
    }
}

// ---------------- phase 2: persistent recurrence, bf16-split mma.sync ----------------
// A = W (96 gate-rows x 512 k), B = h (512 k x 8 b), per CTA/step via m16n8k16.
// Warp w owns k-tiles 4w..4w+3. A frags pre-packed in smem (1 LDS.128 each).
__global__ void __launch_bounds__(BLK_R, 1)
gru_kernel(const float* __restrict__ w_hh,
           const float* __restrict__ b_n_p,
           float* __restrict__ out) {
    extern __shared__ __align__(16) unsigned char smb[];
    uint4* Ahi = (uint4*)(smb + S_AHI);    // [ (mt*32+kt)*32 + lane ]
    uint4* Alo = (uint4*)(smb + S_ALO);
    __nv_bfloat16* Hbase = (__nv_bfloat16*)(smb + S_HP);  // rows: hi b=0..7 then lo b=0..7, stride 520
    float* P = (float*)(smb + S_HP);       // partials alias: [w][m 0..95][b 0..7]

    const int tid  = threadIdx.x;
    const int jb   = blockIdx.x & (NJ - 1);
    const int bg   = blockIdx.x >> 4;
    const int warp = tid >> 5;
    const int lane = tid & 31;
    const int g    = lane >> 2;            // frag group 0..7
    const int iq   = lane & 3;             // frag thread-in-group
    // gate mapping
    const int b_i = tid & 7;
    const int jl  = tid >> 3;              // 0..31
    const int bG  = bg * 8 + b_i;
    const int jG  = jb * 32 + jl;
    const float bn = b_n_p[jG];

    unsigned smHP_addr;
    asm("{ .reg .u64 t0; cvta.to.shared.u64 t0, %1; cvt.u32.u64 %0, t0; }"
        : "=r"(smHP_addr) : "l"((void*)Hbase));

    // ---- stage A fragments once: rows m = gate*32 + jl_, cols k; bf16 hi/lo split ----
    for (int slot = tid; slot < 6 * 32 * 32; slot += BLK_R) {
        int ls  = slot & 31;
        int kt  = (slot >> 5) & 31;
        int mt  = slot >> 10;
        int gs  = ls >> 2, iqs = ls & 3;
        int c0  = kt * 16 + iqs * 2;
        int ra  = mt * 16 + gs;       // row for a0, a2
        int rb  = ra + 8;             // row for a1, a3
        float w00, w01, w10, w11, w02, w03, w12, w13;
        {
            int gate = ra >> 5, j = jb * 32 + (ra & 31);
            const float* row = w_hh + (size_t)(gate * HH + j) * HH;
            w00 = row[c0]; w01 = row[c0 + 1]; w02 = row[c0 + 8]; w03 = row[c0 + 9];
        }
        {
            int gate = rb >> 5, j = jb * 32 + (rb & 31);
            const float* row = w_hh + (size_t)(gate * HH + j) * HH;
            w10 = row[c0]; w11 = row[c0 + 1]; w12 = row[c0 + 8]; w13 = row[c0 + 9];
        }
        __nv_bfloat16 h0, l0, h1, l1, h2, l2, h3, l3, h4, l4, h5, l5, h6, l6, h7, l7;
        bsplit(w00, h0, l0); bsplit(w01, h1, l1);
        bsplit(w10, h2, l2); bsplit(w11, l3 = __nv_bfloat16(), l3), bsplit(w11, h3, l3);
        bsplit(w02, h4, l4); bsplit(w03, h5, l5);
        bsplit(w12, h6, l6); bsplit(w13, h7, l7);
        uint4 vh, vl;
        vh.x = pack2(h0, h1);  vl.x = pack2(l0, l1);   // a0: row ra, k c0,c0+1
        vh.y = pack2(h2, h3);  vl.y = pack2(l2, l3);   // a1: row rb
        vh.z = pack2(h4, h5);  vl.z = pack2(l4, l5);   // a2: row ra, k c0+8,+9
        vh.w = pack2(h6, h7);  vl.w = pack2(l6, l7);   // a3: row rb
        Ahi[slot] = vh;
        Alo[slot] = vl;
    }
    // ---- zero H region (h0 = 0) ----
    for (int idx = tid; idx < 16 * 520; idx += BLK_R)
        Hbase[idx] = __float2bfloat16_rn(0.0f);

    float hreg = 0.0f;

    // preload ig for t=0
    float igr, igz, ign;
    igr = g_ig[((size_t)0 * G3 + 0 * HH + jG) * BB + bG];
    igz = g_ig[((size_t)0 * G3 + 1 * HH + jG) * BB + bG];
    ign = g_ig[((size_t)0 * G3 + 2 * HH + jG) * BB + bG];
    __syncthreads();

    // per-thread B-row pointers (frag col n = b = g); row stride 520 elems
    const __nv_bfloat16* HhiRow = Hbase + g * 520;
    const __nv_bfloat16* HloRow = HhiRow + 8 * 520;
    const uint4* AhiL = Ahi + lane;
    const uint4* AloL = Alo + lane;

    for (int t = 0; t < TT; t++) {
        // prefetch ig for t+1
        float nigr = 0.0f, nigz = 0.0f, nign = 0.0f;
        if (t + 1 < TT) {
            const float* p = g_ig + (size_t)(t + 1) * G3 * BB;
            nigr = p[(size_t)(0 * HH + jG) * BB + bG];
            nigz = p[(size_t)(1 * HH + jG) * BB + bG];
            nign = p[(size_t)(2 * HH + jG) * BB + bG];
        }

        // ---- dot: 4 k-tiles x 6 m-tiles x 3 split terms ----
        float acc[6][4];
#pragma unroll
        for (int mt = 0; mt < 6; mt++)
#pragma unroll
            for (int e = 0; e < 4; e++) acc[mt][e] = 0.0f;

#pragma unroll
        for (int kl = 0; kl < 4; kl++) {
            const int kt = warp * 4 + kl;
            unsigned bh0 = *(const unsigned*)(HhiRow + kt * 16 + iq * 2);
            unsigned bh1 = *(const unsigned*)(HhiRow + kt * 16 + iq * 2 + 8);
            unsigned bl0 = *(const unsigned*)(HloRow + kt * 16 + iq * 2);
            unsigned bl1 = *(const unsigned*)(HloRow + kt * 16 + iq * 2 + 8);
#pragma unroll
            for (int mt = 0; mt < 6; mt++) {
                uint4 ah = AhiL[(mt * 32 + kt) << 5];
                uint4 al = AloL[(mt * 32 + kt) << 5];
                mma_bf16(acc[mt], ah, bh0, bh1);
                mma_bf16(acc[mt], ah, bl0, bl1);
                mma_bf16(acc[mt], al, bh0, bh1);
            }
        }

        __syncthreads();   // all H reads done (partials alias H region)

        // ---- publish partials: P[(warp*96 + m)*8 + b] ----
#pragma unroll
        for (int mt = 0; mt < 6; mt++)
#pragma unroll
            for (int e = 0; e < 4; e++) {
                int m = mt * 16 + g + (e >> 1) * 8;
                int b = iq * 2 + (e & 1);
                P[(warp * 96 + m) * 8 + b] = acc[mt][e];
            }
        __syncthreads();

        // ---- gates: one (jl, b_i) per thread; reduce over 8 warps ----
        float hnew;
        {
            float pr = 0.0f, pz = 0.0f, pn = 0.0f;
#pragma unroll
            for (int w = 0; w < 8; w++) {
                pr += P[(w * 96 +  0 + jl) * 8 + b_i];
                pz += P[(w * 96 + 32 + jl) * 8 + b_i];
                pn += P[(w * 96 + 64 + jl) * 8 + b_i];
            }
            float r = sigmoidf_(igr + pr);
            float z = sigmoidf_(igz + pz);
            float n = tanhf(ign + r * (pn + bn));
            hnew = n + z * (hreg - n);
            hreg = hnew;
        }
        igr = nigr; igz = nigz; ign = nign;

        if (t == TT - 1) {
            out[(size_t)bG * HH + jG] = hnew;
        } else {
            const int nxt = (t + 1) & 1;
            // publish h as bf16 hi/lo planes: row = plane*8 + b, 1024 B per row
            __nv_bfloat16 hh, hl;
            bsplit(hnew, hh, hl);
            *(__nv_bfloat16*)(g_h2[bg][nxt] + (size_t)b_i * 1024 + jG * 2)        = hh;
            *(__nv_bfloat16*)(g_h2[bg][nxt] + (size_t)(8 + b_i) * 1024 + jG * 2)  = hl;
            __syncthreads();   // all STGs issued + all P reads done

            // group barrier (16 CTAs)
            if (tid == 0)
                asm volatile("st.release.gpu.u32 [%0], %1;"
                             :: "l"(g_flags2 + (size_t)(bg * NJ + jb) * 64), "r"(t + 1) : "memory");
            if (tid < NJ) {
                unsigned v;
                do {
                    asm volatile("ld.acquire.gpu.u32 %0, [%1];"
                                 : "=r"(v) : "l"(g_flags2 + (size_t)(bg * NJ + tid) * 64) : "memory");
                } while (v < (unsigned)(t + 1));
            }
            __syncthreads();

            // pull h(t+1): 16 KB -> padded smem rows (1024 B data per 1040 B row)
            {
                const unsigned char* src = g_h2[bg][nxt];
#pragma unroll
                for (int i = 0; i < 4; i++) {
                    int idx = tid + i * BLK_R;          // 0..1023
                    int r   = idx >> 6;
                    int col = idx & 63;
                    cp16(smHP_addr + r * 1040 + col * 16, src + (size_t)idx * 16);
                }
                asm volatile("cp.async.commit_group;");
                asm volatile("cp.async.wait_group 0;");
            }
            __syncthreads();
        }
    }
}

// ---------------- launch ----------------
extern "C" void kernel_launch(void* const* d_in, const int* in_sizes, int n_in,
                              void* d_out, int out_size) {
    const float* xs   = (const float*)d_in[0];
    const float* w_ih = (const float*)d_in[1];
    const float* w_hh = (const float*)d_in[2];
    const float* bias = (const float*)d_in[3];
    const float* b_n  = (const float*)d_in[4];
    float* out = (float*)d_out;

    cudaFuncSetAttribute(gru_kernel,
                         cudaFuncAttributeMaxDynamicSharedMemorySize, SMEM_BYTES);
    cudaFuncSetAttribute(ig_tensor_kernel,
                         cudaFuncAttributeMaxDynamicSharedMemorySize, IGT_SMEMB);

    reset_kernel<<<1, 128>>>();

    dim3 g1(TT, G3 / 128);
    ig_tensor_kernel<<<g1, 256, IGT_SMEMB>>>(xs, w_ih, bias);

    gru_kernel<<<NJ * NB, BLK_R, SMEM_BYTES>>>(w_hh, b_n, out);
}

// round 15
// speedup vs baseline: 1.4968x; 1.4968x over previous
#include <cuda_runtime.h>
#include <cuda_bf16.h>
#include <math.h>

#define BB 64
#define TT 2048
#define II 256
#define HH 512
#define G3 1536          // 3*H

// recurrent grid: 16 j-CTAs x 8 b-groups = 128 CTAs (co-resident)
#define NJ 16            // j-blocks (32 j each)
#define NB 8             // b-groups (8 b each)
#define BLK_R 256        // 8 warps; warp = 64-k slice (4 k-tiles of 16)

// gru smem (bytes):
//   [0, 98304)        A lo fragments: uint4[6*32*32]  (96 KB)
//   [98304, 122880)   H bf16 hi/lo planes (16 rows x 520 elems x 2 B = 16640 B)
//                     aliased by partials float[8*96*8] = 24576 B
#define S_ALO 0
#define S_HP  98304
#define SMEM_BYTES (98304 + 24576)   // 122880

// ig tensor kernel smem (floats), padded stride 68 for conflict-free frags
#define WST   68
#define S_WHI 0
#define S_WLO 8704
#define S_XHI 17408
#define S_XLO 21760
#define IGT_SMEMF 26112
#define IGT_SMEMB (IGT_SMEMF * 4)

// ---------------- scratch ----------------
__device__ float g_ig[(size_t)TT * G3 * BB];           // [t][j][b]
__device__ __align__(16) unsigned char g_h2[NB][2][16384]; // [buf]: 16 rows(plane*8+b) x 1024 B
__device__ unsigned g_flags2[NB * NJ * 64];            // 256-B padded flags

// ---------------- helpers ----------------
__device__ __forceinline__ float sigmoidf_(float x) {
    return 1.0f / (1.0f + expf(-x));
}
__device__ __forceinline__ void cp16(unsigned dst, const void* src) {
    asm volatile("cp.async.cg.shared.global [%0], [%1], 16;" :: "r"(dst), "l"(src));
}
__device__ __forceinline__ unsigned f2tf32(float x) {
    unsigned u;
    asm("cvt.rna.tf32.f32 %0, %1;" : "=r"(u) : "f"(x));
    return u;
}
__device__ __forceinline__ void mma_tf32(float* c, const unsigned* a, const unsigned* b) {
    asm volatile(
        "mma.sync.aligned.m16n8k8.row.col.f32.tf32.tf32.f32 "
        "{%0,%1,%2,%3}, {%4,%5,%6,%7}, {%8,%9}, {%0,%1,%2,%3};"
        : "+f"(c[0]), "+f"(c[1]), "+f"(c[2]), "+f"(c[3])
        : "r"(a[0]), "r"(a[1]), "r"(a[2]), "r"(a[3]), "r"(b[0]), "r"(b[1]));
}
__device__ __forceinline__ void mma_bf16(float* c, uint4 a, unsigned b0, unsigned b1) {
    asm volatile(
        "mma.sync.aligned.m16n8k16.row.col.f32.bf16.bf16.f32 "
        "{%0,%1,%2,%3}, {%4,%5,%6,%7}, {%8,%9}, {%0,%1,%2,%3};"
        : "+f"(c[0]), "+f"(c[1]), "+f"(c[2]), "+f"(c[3])
        : "r"(a.x), "r"(a.y), "r"(a.z), "r"(a.w), "r"(b0), "r"(b1));
}
__device__ __forceinline__ void bsplit(float x, __nv_bfloat16& h, __nv_bfloat16& l) {
    h = __float2bfloat16_rn(x);
    l = __float2bfloat16_rn(x - __bfloat162float(h));
}
__device__ __forceinline__ unsigned pack2(__nv_bfloat16 e0, __nv_bfloat16 e1) {
    return (unsigned)__bfloat16_as_ushort(e0) | ((unsigned)__bfloat16_as_ushort(e1) << 16);
}

// ---------------- reset ----------------
__global__ void reset_kernel() {
    int idx = blockIdx.x * blockDim.x + threadIdx.x;
    if (idx < NB * NJ) g_flags2[idx * 64] = 0;
}

// ---------------- phase 1: IG via tf32-split tensor cores (unchanged) ----------------
__global__ void __launch_bounds__(256, 2)
ig_tensor_kernel(const float* __restrict__ xs,
                 const float* __restrict__ w_ih,
                 const float* __restrict__ bias) {
    extern __shared__ __align__(16) float sm[];
    float* Whi = sm + S_WHI;
    float* Wlo = sm + S_WLO;
    float* Xhi = sm + S_XHI;
    float* Xlo = sm + S_XLO;

    const int t    = blockIdx.x;
    const int jb   = blockIdx.y * 128;
    const int tid  = threadIdx.x;
    const int warp = tid >> 5;
    const int lane = tid & 31;
    const int wj   = warp >> 1;
    const int wb   = warp & 1;
    const int g    = lane >> 2;
    const int iq   = lane & 3;

    float acc[2][4][4];
#pragma unroll
    for (int mt = 0; mt < 2; mt++)
#pragma unroll
        for (int nt = 0; nt < 4; nt++)
#pragma unroll
            for (int e = 0; e < 4; e++) acc[mt][nt][e] = 0.0f;

    for (int kc = 0; kc < II; kc += 64) {
        {
            int r = tid >> 1, hf = tid & 1;
            const float* src = w_ih + (size_t)(jb + r) * II + kc + hf * 32;
            float* dh = Whi + r * WST + hf * 32;
            float* dl = Wlo + r * WST + hf * 32;
#pragma unroll
            for (int q = 0; q < 8; q++) {
                float4 v = *(const float4*)(src + q * 4);
                float xv[4] = {v.x, v.y, v.z, v.w};
#pragma unroll
                for (int e = 0; e < 4; e++) {
                    unsigned hu = f2tf32(xv[e]);
                    float hif = __uint_as_float(hu);
                    dh[q * 4 + e] = hif;
                    dl[q * 4 + e] = __uint_as_float(f2tf32(xv[e] - hif));
                }
            }
        }
        {
            int b = tid >> 2, q = tid & 3;
            const float* src = xs + ((size_t)b * TT + t) * II + kc + q * 16;
#pragma unroll
            for (int v = 0; v < 4; v++) {
                float4 x4 = *(const float4*)(src + v * 4);
                float xv[4] = {x4.x, x4.y, x4.z, x4.w};
                int k = q * 16 + v * 4;
#pragma unroll
                for (int e = 0; e < 4; e++) {
                    unsigned hu = f2tf32(xv[e]);
                    float hif = __uint_as_float(hu);
                    Xhi[(k + e) * WST + b] = hif;
                    Xlo[(k + e) * WST + b] = __uint_as_float(f2tf32(xv[e] - hif));
                }
            }
        }
        __syncthreads();

#pragma unroll
        for (int ks = 0; ks < 8; ks++) {
            const int k0 = ks * 8;
            unsigned ah[2][4], al[2][4];
#pragma unroll
            for (int mt = 0; mt < 2; mt++) {
                int jr = wj * 32 + mt * 16;
                ah[mt][0] = __float_as_uint(Whi[(jr + g)     * WST + k0 + iq]);
                ah[mt][1] = __float_as_uint(Whi[(jr + g + 8) * WST + k0 + iq]);
                ah[mt][2] = __float_as_uint(Whi[(jr + g)     * WST + k0 + iq + 4]);
                ah[mt][3] = __float_as_uint(Whi[(jr + g + 8) * WST + k0 + iq + 4]);
                al[mt][0] = __float_as_uint(Wlo[(jr + g)     * WST + k0 + iq]);
                al[mt][1] = __float_as_uint(Wlo[(jr + g + 8) * WST + k0 + iq]);
                al[mt][2] = __float_as_uint(Wlo[(jr + g)     * WST + k0 + iq + 4]);
                al[mt][3] = __float_as_uint(Wlo[(jr + g + 8) * WST + k0 + iq + 4]);
            }
            unsigned bh[4][2], bl[4][2];
#pragma unroll
            for (int nt = 0; nt < 4; nt++) {
                int bc = wb * 32 + nt * 8;
                bh[nt][0] = __float_as_uint(Xhi[(k0 + iq)     * WST + bc + g]);
                bh[nt][1] = __float_as_uint(Xhi[(k0 + iq + 4) * WST + bc + g]);
                bl[nt][0] = __float_as_uint(Xlo[(k0 + iq)     * WST + bc + g]);
                bl[nt][1] = __float_as_uint(Xlo[(k0 + iq + 4) * WST + bc + g]);
            }
#pragma unroll
            for (int mt = 0; mt < 2; mt++)
#pragma unroll
                for (int nt = 0; nt < 4; nt++) {
                    mma_tf32(acc[mt][nt], ah[mt], bh[nt]);
                    mma_tf32(acc[mt][nt], ah[mt], bl[nt]);
                    mma_tf32(acc[mt][nt], al[mt], bh[nt]);
                }
        }
        __syncthreads();
    }

#pragma unroll
    for (int mt = 0; mt < 2; mt++) {
#pragma unroll
        for (int rr = 0; rr < 2; rr++) {
            int j = jb + wj * 32 + mt * 16 + g + rr * 8;
            float bj = bias[j];
#pragma unroll
            for (int nt = 0; nt < 4; nt++) {
                int bc = wb * 32 + nt * 8 + 2 * iq;
                float2 o = make_float2(acc[mt][nt][rr * 2 + 0] + bj,
                                       acc[mt][nt][rr * 2 + 1] + bj);
                *(float2*)&g_ig[((size_t)t * G3 + j) * BB + bc] = o;
            }
        }
    }
}

// ---------------- phase 2: persistent recurrence, bf16-split mma.sync ----------------
// A hi fragments register-resident (24 uint4/thread); A lo in smem; B conflict-free.
__global__ void __launch_bounds__(BLK_R, 1)
gru_kernel(const float* __restrict__ w_hh,
           const float* __restrict__ b_n_p,
           float* __restrict__ out) {
    extern __shared__ __align__(16) unsigned char smb[];
    uint4* Alo = (uint4*)(smb + S_ALO);    // [(mt*32+kt)*32 + lane]
    __nv_bfloat16* Hbase = (__nv_bfloat16*)(smb + S_HP);  // 16 rows x 520, hi b=0..7 then lo
    float* P = (float*)(smb + S_HP);       // partials alias: [w][m 0..95][b 0..7]

    const int tid  = threadIdx.x;
    const int jb   = blockIdx.x & (NJ - 1);
    const int bg   = blockIdx.x >> 4;
    const int warp = tid >> 5;
    const int lane = tid & 31;
    const int g    = lane >> 2;
    const int iq   = lane & 3;
    const int b_i = tid & 7;
    const int jl  = tid >> 3;
    const int bG  = bg * 8 + b_i;
    const int jG  = jb * 32 + jl;
    const float bn = b_n_p[jG];

    unsigned smHP_addr;
    asm("{ .reg .u64 t0; cvta.to.shared.u64 t0, %1; cvt.u32.u64 %0, t0; }"
        : "=r"(smHP_addr) : "l"((void*)Hbase));

    // ---- build this thread's A fragments: hi -> registers, lo -> smem ----
    uint4 ah[6][4];
#pragma unroll
    for (int mt = 0; mt < 6; mt++) {
#pragma unroll
        for (int kl = 0; kl < 4; kl++) {
            const int kt = warp * 4 + kl;
            const int c0 = kt * 16 + iq * 2;
            const int ra = mt * 16 + g;
            const int rb = ra + 8;
            const int gateA = ra >> 5, jA = jb * 32 + (ra & 31);
            const int gateB = rb >> 5, jB = jb * 32 + (rb & 31);
            const float* rowA = w_hh + (size_t)(gateA * HH + jA) * HH;
            const float* rowB = w_hh + (size_t)(gateB * HH + jB) * HH;
            float2 a01 = *(const float2*)(rowA + c0);
            float2 a89 = *(const float2*)(rowA + c0 + 8);
            float2 b01 = *(const float2*)(rowB + c0);
            float2 b89 = *(const float2*)(rowB + c0 + 8);
            __nv_bfloat16 h0, l0, h1, l1, h2, l2, h3, l3;
            __nv_bfloat16 h4, l4, h5, l5, h6, l6, h7, l7;
            bsplit(a01.x, h0, l0); bsplit(a01.y, h1, l1);
            bsplit(b01.x, h2, l2); bsplit(b01.y, h3, l3);
            bsplit(a89.x, h4, l4); bsplit(a89.y, h5, l5);
            bsplit(b89.x, h6, l6); bsplit(b89.y, h7, l7);
            uint4 vh, vl;
            vh.x = pack2(h0, h1);  vl.x = pack2(l0, l1);   // a0: row ra, k c0,c0+1
            vh.y = pack2(h2, h3);  vl.y = pack2(l2, l3);   // a1: row rb
            vh.z = pack2(h4, h5);  vl.z = pack2(l4, l5);   // a2: row ra, k c0+8,+9
            vh.w = pack2(h6, h7);  vl.w = pack2(l6, l7);   // a3: row rb
            ah[mt][kl] = vh;
            Alo[(mt * 32 + kt) * 32 + lane] = vl;
        }
    }
    // ---- zero H region (h0 = 0) ----
    for (int idx = tid; idx < 16 * 520; idx += BLK_R)
        Hbase[idx] = __float2bfloat16_rn(0.0f);

    float hreg = 0.0f;

    // preload ig for t=0
    float igr, igz, ign;
    igr = g_ig[((size_t)0 * G3 + 0 * HH + jG) * BB + bG];
    igz = g_ig[((size_t)0 * G3 + 1 * HH + jG) * BB + bG];
    ign = g_ig[((size_t)0 * G3 + 2 * HH + jG) * BB + bG];
    __syncthreads();

    const __nv_bfloat16* HhiRow = Hbase + g * 520;
    const __nv_bfloat16* HloRow = HhiRow + 8 * 520;
    const uint4* AloL = Alo + lane;

    for (int t = 0; t < TT; t++) {
        // prefetch ig for t+1
        float nigr = 0.0f, nigz = 0.0f, nign = 0.0f;
        if (t + 1 < TT) {
            const float* p = g_ig + (size_t)(t + 1) * G3 * BB;
            nigr = p[(size_t)(0 * HH + jG) * BB + bG];
            nigz = p[(size_t)(1 * HH + jG) * BB + bG];
            nign = p[(size_t)(2 * HH + jG) * BB + bG];
        }

        // ---- dot: 4 k-tiles x 6 m-tiles x 3 split terms ----
        float acc[6][4];
#pragma unroll
        for (int mt = 0; mt < 6; mt++)
#pragma unroll
            for (int e = 0; e < 4; e++) acc[mt][e] = 0.0f;

#pragma unroll
        for (int kl = 0; kl < 4; kl++) {
            const int kt = warp * 4 + kl;
            unsigned bh0 = *(const unsigned*)(HhiRow + kt * 16 + iq * 2);
            unsigned bh1 = *(const unsigned*)(HhiRow + kt * 16 + iq * 2 + 8);
            unsigned bl0 = *(const unsigned*)(HloRow + kt * 16 + iq * 2);
            unsigned bl1 = *(const unsigned*)(HloRow + kt * 16 + iq * 2 + 8);
#pragma unroll
            for (int mt = 0; mt < 6; mt++) {
                uint4 al = AloL[(mt * 32 + kt) << 5];
                mma_bf16(acc[mt], ah[mt][kl], bh0, bh1);
                mma_bf16(acc[mt], al,         bh0, bh1);
                mma_bf16(acc[mt], ah[mt][kl], bl0, bl1);
            }
        }

        __syncthreads();   // all H reads done (partials alias H region)

        // ---- publish partials: P[(warp*96 + m)*8 + b] ----
#pragma unroll
        for (int mt = 0; mt < 6; mt++)
#pragma unroll
            for (int e = 0; e < 4; e++) {
                int m = mt * 16 + g + (e >> 1) * 8;
                int b = iq * 2 + (e & 1);
                P[(warp * 96 + m) * 8 + b] = acc[mt][e];
            }
        __syncthreads();

        // ---- gates: one (jl, b_i) per thread; reduce over 8 warps ----
        float hnew;
        {
            float pr = 0.0f, pz = 0.0f, pn = 0.0f;
#pragma unroll
            for (int w = 0; w < 8; w++) {
                pr += P[(w * 96 +  0 + jl) * 8 + b_i];
                pz += P[(w * 96 + 32 + jl) * 8 + b_i];
                pn += P[(w * 96 + 64 + jl) * 8 + b_i];
            }
            float r = sigmoidf_(igr + pr);
            float z = sigmoidf_(igz + pz);
            float n = tanhf(ign + r * (pn + bn));
            hnew = n + z * (hreg - n);
            hreg = hnew;
        }
        igr = nigr; igz = nigz; ign = nign;

        if (t == TT - 1) {
            out[(size_t)bG * HH + jG] = hnew;
        } else {
            const int nxt = (t + 1) & 1;
            __nv_bfloat16 hh, hl;
            bsplit(hnew, hh, hl);
            *(__nv_bfloat16*)(g_h2[bg][nxt] + (size_t)b_i * 1024 + jG * 2)        = hh;
            *(__nv_bfloat16*)(g_h2[bg][nxt] + (size_t)(8 + b_i) * 1024 + jG * 2)  = hl;
            __syncthreads();   // all STGs issued + all P reads done

            // group barrier (16 CTAs)
            if (tid == 0)
                asm volatile("st.release.gpu.u32 [%0], %1;"
                             :: "l"(g_flags2 + (size_t)(bg * NJ + jb) * 64), "r"(t + 1) : "memory");
            if (tid < NJ) {
                unsigned v;
                do {
                    asm volatile("ld.acquire.gpu.u32 %0, [%1];"
                                 : "=r"(v) : "l"(g_flags2 + (size_t)(bg * NJ + tid) * 64) : "memory");
                } while (v < (unsigned)(t + 1));
            }
            __syncthreads();

            // pull h(t+1): 16 KB -> padded smem rows (1024 B data per 1040 B row)
            {
                const unsigned char* src = g_h2[bg][nxt];
#pragma unroll
                for (int i = 0; i < 4; i++) {
                    int idx = tid + i * BLK_R;          // 0..1023
                    int r   = idx >> 6;
                    int col = idx & 63;
                    cp16(smHP_addr + r * 1040 + col * 16, src + (size_t)idx * 16);
                }
                asm volatile("cp.async.commit_group;");
                asm volatile("cp.async.wait_group 0;");
            }
            __syncthreads();
        }
    }
}

// ---------------- launch ----------------
extern "C" void kernel_launch(void* const* d_in, const int* in_sizes, int n_in,
                              void* d_out, int out_size) {
    const float* xs   = (const float*)d_in[0];
    const float* w_ih = (const float*)d_in[1];
    const float* w_hh = (const float*)d_in[2];
    const float* bias = (const float*)d_in[3];
    const float* b_n  = (const float*)d_in[4];
    float* out = (float*)d_out;

    cudaFuncSetAttribute(gru_kernel,
                         cudaFuncAttributeMaxDynamicSharedMemorySize, SMEM_BYTES);
    cudaFuncSetAttribute(ig_tensor_kernel,
                         cudaFuncAttributeMaxDynamicSharedMemorySize, IGT_SMEMB);

    reset_kernel<<<1, 128>>>();

    dim3 g1(TT, G3 / 128);
    ig_tensor_kernel<<<g1, 256, IGT_SMEMB>>>(xs, w_ih, bias);

    gru_kernel<<<NJ * NB, BLK_R, SMEM_BYTES>>>(w_hh, b_n, out);
}